// round 1
// baseline (speedup 1.0000x reference)
#include <cuda_runtime.h>
#include <cuda_bf16.h>

#define B_ 64
#define T_ 1024
#define I_ 8
#define H_ 512
#define O_ 2
#define R_ 2
#define NOISE_STD_ 0.05f
#define ALPHA_ 0.2f

// tanh(x) = 1 - 2/(exp(2x)+1) via MUFU ex2/rcp. ~1e-6 abs error, handles +-inf
// saturation correctly (ex2->inf => rcp->0 => +1 ; ex2->0 => 1-2*1 = -1).
__device__ __forceinline__ float tanh_fast(float x) {
    float e;
    asm("ex2.approx.f32 %0, %1;" : "=f"(e) : "f"(x * 2.8853900817779268f)); // 2*log2(e)
    float rr;
    asm("rcp.approx.f32 %0, %1;" : "=f"(rr) : "f"(e + 1.0f));
    return fmaf(-2.0f, rr, 1.0f);
}

__global__ __launch_bounds__(512, 1)
void lowrank_rnn_kernel(const float* __restrict__ input,   // (B,T,I)
                        const float* __restrict__ noise,   // (B,T,H)
                        const float* __restrict__ wi,      // (I,H)
                        const float* __restrict__ si,      // (I,)
                        const float* __restrict__ m,       // (H,R)
                        const float* __restrict__ n,       // (H,R)
                        const float* __restrict__ wo,      // (H,O)
                        const float* __restrict__ so,      // (O,)
                        const float* __restrict__ h0,      // (H,)
                        float* __restrict__ out,           // (B,T,O)
                        float* __restrict__ traj)          // (B,T,H)
{
    __shared__ float  s_in[T_ * I_];       // 32 KB: whole input row for this batch
    __shared__ float2 s_a[2][16];          // per-warp partials of r.n0, r.n1 (double buffered)
    __shared__ float2 s_o[2][16];          // per-warp partials of r.wo0, r.wo1

    const int b    = blockIdx.x;
    const int k    = threadIdx.x;          // hidden index
    const int warp = k >> 5;
    const int lane = k & 31;

    // ---- stage input (B-th row) into smem, coalesced float4 ----
    {
        const float4* gin  = (const float4*)(input + (size_t)b * T_ * I_);
        float4*       sin4 = (float4*)s_in;
        #pragma unroll
        for (int i = 0; i < (T_ * I_ / 4) / 512; ++i)      // 4 iters
            sin4[k + i * 512] = gin[k + i * 512];
    }

    // ---- per-thread weight registers ----
    float wif[I_];
    #pragma unroll
    for (int i = 0; i < I_; ++i) wif[i] = wi[i * H_ + k] * si[i];
    const float m0  = m[k * R_ + 0],  m1  = m[k * R_ + 1];
    const float n0  = n[k * R_ + 0],  n1  = n[k * R_ + 1];
    const float wo0 = wo[k * O_ + 0] * so[0];
    const float wo1 = wo[k * O_ + 1] * so[1];
    const float invH = 1.0f / (float)H_;

    float h = h0[k];
    float r = tanh_fast(h);

    const float* nz_ptr   = noise + (size_t)b * T_ * H_ + k;
    float*       traj_ptr = traj  + (size_t)b * T_ * H_ + k;
    float*       out_ptr  = out   + (size_t)b * T_ * O_;

    // noise prefetch pipeline (depth 2)
    float nzA = nz_ptr[0];
    float nzB = nz_ptr[H_];

    // ---- pre-loop: initial recurrence dots a = n^T r_0 (use buffer 1) ----
    {
        float pa0 = r * n0, pa1 = r * n1;
        #pragma unroll
        for (int d = 16; d > 0; d >>= 1) {
            pa0 += __shfl_xor_sync(0xffffffffu, pa0, d);
            pa1 += __shfl_xor_sync(0xffffffffu, pa1, d);
        }
        if (lane == 0) s_a[1][warp] = make_float2(pa0, pa1);
    }
    __syncthreads();   // covers s_in staging + initial partials

    float a0, a1;
    {
        const float4* pa4 = (const float4*)s_a[1];
        float4 acc = pa4[0];
        #pragma unroll
        for (int i = 1; i < 8; ++i) {
            float4 v = pa4[i];
            acc.x += v.x; acc.y += v.y; acc.z += v.z; acc.w += v.w;
        }
        a0 = acc.x + acc.z;
        a1 = acc.y + acc.w;
    }

    // ---- main scan ----
    #pragma unroll 1
    for (int t = 0; t < T_; ++t) {
        const float nz = nzA;
        nzA = nzB;
        nzB = (t + 2 < T_) ? nz_ptr[(size_t)(t + 2) * H_] : 0.0f;

        // input projection p_t (smem broadcast, conflict-free)
        const float* row = s_in + t * I_;
        const float4 i0 = *(const float4*)(row);
        const float4 i1 = *(const float4*)(row + 4);
        float p = i0.x * wif[0];
        p = fmaf(i0.y, wif[1], p);
        p = fmaf(i0.z, wif[2], p);
        p = fmaf(i0.w, wif[3], p);
        p = fmaf(i1.x, wif[4], p);
        p = fmaf(i1.y, wif[5], p);
        p = fmaf(i1.z, wif[6], p);
        p = fmaf(i1.w, wif[7], p);

        // rank-2 recurrent drive from carried dots (uses r_t via a0,a1)
        const float rec = (fmaf(a0, m0, a1 * m1)) * invH;

        // h_{t+1} = h + sigma*nz + alpha*(-h + rec + p)
        h = fmaf(ALPHA_, (rec + p) - h, h);
        h = fmaf(NOISE_STD_, nz, h);

        traj_ptr[(size_t)t * H_] = h;      // traj[t] = h_{t+1}, coalesced STG

        r = tanh_fast(h);                  // r_{t+1}

        // fused 4-value block reduction: a (next step) + o (out[t])
        float pa0 = r * n0, pa1 = r * n1, po0 = r * wo0, po1 = r * wo1;
        #pragma unroll
        for (int d = 16; d > 0; d >>= 1) {
            pa0 += __shfl_xor_sync(0xffffffffu, pa0, d);
            pa1 += __shfl_xor_sync(0xffffffffu, pa1, d);
            po0 += __shfl_xor_sync(0xffffffffu, po0, d);
            po1 += __shfl_xor_sync(0xffffffffu, po1, d);
        }
        const int buf = t & 1;
        if (lane == 0) {
            s_a[buf][warp] = make_float2(pa0, pa1);
            s_o[buf][warp] = make_float2(po0, po1);
        }
        __syncthreads();                   // single bar per step (double-buffered)

        // redundant per-thread sum of 16 warp partials (no broadcast needed)
        {
            const float4* pa4 = (const float4*)s_a[buf];
            float4 acc = pa4[0];
            #pragma unroll
            for (int i = 1; i < 8; ++i) {
                float4 v = pa4[i];
                acc.x += v.x; acc.y += v.y; acc.z += v.z; acc.w += v.w;
            }
            a0 = acc.x + acc.z;
            a1 = acc.y + acc.w;
        }

        if (k == 0) {
            const float4* po4 = (const float4*)s_o[buf];
            float4 acc = po4[0];
            #pragma unroll
            for (int i = 1; i < 8; ++i) {
                float4 v = po4[i];
                acc.x += v.x; acc.y += v.y; acc.z += v.z; acc.w += v.w;
            }
            const float o0 = (acc.x + acc.z) * invH;
            const float o1 = (acc.y + acc.w) * invH;
            *(float2*)(out_ptr + (size_t)t * O_) = make_float2(o0, o1);
        }
    }
}

extern "C" void kernel_launch(void* const* d_in, const int* in_sizes, int n_in,
                              void* d_out, int out_size) {
    const float* input = (const float*)d_in[0];
    const float* noise = (const float*)d_in[1];
    const float* wi    = (const float*)d_in[2];
    const float* si    = (const float*)d_in[3];
    const float* m     = (const float*)d_in[4];
    const float* n     = (const float*)d_in[5];
    const float* wo    = (const float*)d_in[6];
    const float* so    = (const float*)d_in[7];
    const float* h0    = (const float*)d_in[8];

    float* out  = (float*)d_out;                    // (B,T,O) first
    float* traj = (float*)d_out + (size_t)B_ * T_ * O_;  // then (B,T,H)

    lowrank_rnn_kernel<<<B_, 512>>>(input, noise, wi, si, m, n, wo, so, h0,
                                    out, traj);
}

// round 3
// speedup vs baseline: 1.4816x; 1.4816x over previous
#include <cuda_runtime.h>
#include <cuda_bf16.h>

#define B_ 64
#define T_ 1024
#define I_ 8
#define H_ 512
#define O_ 2
#define NOISE_STD_ 0.05f
#define ALPHA_ 0.2f

#define NT_  128            // threads per CTA
#define UPT_ 4              // hidden units per thread (NT_*UPT_ == H_)
#define NW_  (NT_ / 32)     // 4 warps

// tanh(x) = 1 - 2/(exp(2x)+1) via MUFU ex2/rcp. ~1e-6 abs error, saturates
// correctly at +-inf.
__device__ __forceinline__ float tanh_fast(float x) {
    float e;
    asm("ex2.approx.f32 %0, %1;" : "=f"(e) : "f"(x * 2.8853900817779268f)); // 2*log2(e)
    float rr;
    asm("rcp.approx.f32 %0, %1;" : "=f"(rr) : "f"(e + 1.0f));
    return fmaf(-2.0f, rr, 1.0f);
}

// Packed 2xf32 add (Blackwell f32x2 pipe).
__device__ __forceinline__ unsigned long long add_f32x2(unsigned long long a,
                                                        unsigned long long b) {
    unsigned long long r;
    asm("add.rn.f32x2 %0, %1, %2;" : "=l"(r) : "l"(a), "l"(b));
    return r;
}

__device__ __forceinline__ unsigned long long pack2(float x, float y) {
    unsigned long long r;
    asm("mov.b64 %0, {%1, %2};" : "=l"(r) : "f"(x), "f"(y));
    return r;
}

__device__ __forceinline__ void unpack2(unsigned long long v, float& x, float& y) {
    asm("mov.b64 {%0, %1}, %2;" : "=f"(x), "=f"(y) : "l"(v));
}

// Butterfly-xor step on a packed pair: shuffle both halves, packed add.
__device__ __forceinline__ unsigned long long bfly_add_f32x2(unsigned long long v, int d) {
    const unsigned lo = (unsigned)v, hi = (unsigned)(v >> 32);
    const unsigned olo = __shfl_xor_sync(0xffffffffu, lo, d);
    const unsigned ohi = __shfl_xor_sync(0xffffffffu, hi, d);
    return add_f32x2(v, ((unsigned long long)ohi << 32) | olo);
}

__global__ __launch_bounds__(NT_, 1)
void lowrank_rnn_kernel(const float* __restrict__ input,   // (B,T,I)
                        const float* __restrict__ noise,   // (B,T,H)
                        const float* __restrict__ wi,      // (I,H)
                        const float* __restrict__ si,      // (I,)
                        const float* __restrict__ m,       // (H,R)
                        const float* __restrict__ n,       // (H,R)
                        const float* __restrict__ wo,      // (H,O)
                        const float* __restrict__ so,      // (O,)
                        const float* __restrict__ h0,      // (H,)
                        float* __restrict__ out,           // (B,T,O)
                        float* __restrict__ traj)          // (B,T,H)
{
    __shared__ float  s_in[T_ * I_];         // 32 KB: full input row for this batch
    __shared__ float4 s_red[2][NW_];         // per-warp partials (a0,a1,o0,o1), dbl-buffered

    const int b    = blockIdx.x;
    const int tid  = threadIdx.x;
    const int warp = tid >> 5;
    const int lane = tid & 31;
    const int k0   = tid * UPT_;             // first hidden unit of this thread

    // ---- stage input into smem, coalesced float4 ----
    {
        const float4* gin  = (const float4*)(input + (size_t)b * T_ * I_);
        float4*       sin4 = (float4*)s_in;
        #pragma unroll
        for (int i = 0; i < (T_ * I_ / 4) / NT_; ++i)     // 16 iters
            sin4[tid + i * NT_] = gin[tid + i * NT_];
    }

    // ---- per-thread weights (folded constants) ----
    float wif[I_][UPT_];
    #pragma unroll
    for (int i = 0; i < I_; ++i) {
        const float4 w = *(const float4*)(wi + i * H_ + k0);
        const float  s = si[i];
        wif[i][0] = w.x * s; wif[i][1] = w.y * s;
        wif[i][2] = w.z * s; wif[i][3] = w.w * s;
    }
    const float cm  = ALPHA_ / (float)H_;          // alpha/H folded into m
    const float so0 = so[0] / (float)H_;           // 1/H folded into wo
    const float so1 = so[1] / (float)H_;
    float m0f[UPT_], m1f[UPT_], n0f[UPT_], n1f[UPT_], wo0f[UPT_], wo1f[UPT_];
    #pragma unroll
    for (int j = 0; j < UPT_; ++j) {
        const int k = k0 + j;
        m0f[j]  = m[k * 2 + 0] * cm;   m1f[j]  = m[k * 2 + 1] * cm;
        n0f[j]  = n[k * 2 + 0];        n1f[j]  = n[k * 2 + 1];
        wo0f[j] = wo[k * 2 + 0] * so0; wo1f[j] = wo[k * 2 + 1] * so1;
    }

    float h[UPT_];
    {
        const float4 hh = *(const float4*)(h0 + k0);
        h[0] = hh.x; h[1] = hh.y; h[2] = hh.z; h[3] = hh.w;
    }

    const float* nz_base   = noise + (size_t)b * T_ * H_ + k0;
    float*       traj_base = traj  + (size_t)b * T_ * H_ + k0;
    float*       out_base  = out   + (size_t)b * T_ * O_;

    // ---- noise prefetch ring, depth 4 ----
    float4 ring[4];
    #pragma unroll
    for (int j = 0; j < 4; ++j)
        ring[j] = *(const float4*)(nz_base + (size_t)j * H_);

    // ---- pre-loop: a = n^T r_0 (into buffer 1; loop iter 0 writes buffer 0) ----
    float a0, a1;
    {
        float pa0 = 0.0f, pa1 = 0.0f;
        #pragma unroll
        for (int u = 0; u < UPT_; ++u) {
            const float r = tanh_fast(h[u]);
            pa0 = fmaf(r, n0f[u], pa0);
            pa1 = fmaf(r, n1f[u], pa1);
        }
        unsigned long long va = pack2(pa0, pa1);
        #pragma unroll
        for (int d = 16; d > 0; d >>= 1) va = bfly_add_f32x2(va, d);
        unpack2(va, pa0, pa1);
        if (lane == 0) s_red[1][warp] = make_float4(pa0, pa1, 0.0f, 0.0f);
        __syncthreads();                 // also covers s_in staging
        float4 acc = s_red[1][0];
        #pragma unroll
        for (int w = 1; w < NW_; ++w) {
            const float4 v = s_red[1][w];
            acc.x += v.x; acc.y += v.y;
        }
        a0 = acc.x; a1 = acc.y;
    }

    // ---- main scan ----
    #pragma unroll 4
    for (int t = 0; t < T_; ++t) {
        const int j = t & 3;
        const float4 nz = ring[j];
        int tp = t + 4; if (tp > T_ - 1) tp = T_ - 1;            // clamp tail
        ring[j] = *(const float4*)(nz_base + (size_t)tp * H_);   // prefetch t+4

        // input projection p_t for 4 units (smem broadcast reads)
        const float4 i0 = *(const float4*)(s_in + t * I_);
        const float4 i1 = *(const float4*)(s_in + t * I_ + 4);
        float p[UPT_];
        #pragma unroll
        for (int u = 0; u < UPT_; ++u) {
            float pp = i0.x * wif[0][u];
            pp = fmaf(i0.y, wif[1][u], pp);
            pp = fmaf(i0.z, wif[2][u], pp);
            pp = fmaf(i0.w, wif[3][u], pp);
            pp = fmaf(i1.x, wif[4][u], pp);
            pp = fmaf(i1.y, wif[5][u], pp);
            pp = fmaf(i1.z, wif[6][u], pp);
            pp = fmaf(i1.w, wif[7][u], pp);
            p[u] = pp;
        }
        const float nza[UPT_] = {nz.x, nz.y, nz.z, nz.w};

        // h' = 0.8h + 0.05nz + 0.2p + a0*(0.2/H)m0 + a1*(0.2/H)m1 ; r' = tanh(h')
        float pa0 = 0.0f, pa1 = 0.0f, po0 = 0.0f, po1 = 0.0f;
        #pragma unroll
        for (int u = 0; u < UPT_; ++u) {
            const float base = fmaf(NOISE_STD_, nza[u], ALPHA_ * p[u]);  // off crit path
            const float hb   = fmaf(1.0f - ALPHA_, h[u], base);          // off crit path
            float hx = fmaf(a0, m0f[u], hb);                             // crit path: 2 FMA
            hx       = fmaf(a1, m1f[u], hx);
            h[u] = hx;
            const float r = tanh_fast(hx);
            pa0 = fmaf(r, n0f[u], pa0);
            pa1 = fmaf(r, n1f[u], pa1);
            po0 = fmaf(r, wo0f[u], po0);
            po1 = fmaf(r, wo1f[u], po1);
        }

        // traj[t] = h_{t+1}, coalesced STG.128
        *(float4*)(traj_base + (size_t)t * H_) = make_float4(h[0], h[1], h[2], h[3]);

        // warp reduction: packed f32x2 butterfly (a-pair on the critical path)
        unsigned long long va = pack2(pa0, pa1);
        unsigned long long vo = pack2(po0, po1);
        #pragma unroll
        for (int d = 16; d > 0; d >>= 1) {
            va = bfly_add_f32x2(va, d);
            vo = bfly_add_f32x2(vo, d);
        }
        unpack2(va, pa0, pa1);
        unpack2(vo, po0, po1);

        const int buf = t & 1;
        if (lane == 0) s_red[buf][warp] = make_float4(pa0, pa1, po0, po1);
        __syncthreads();                  // one bar per step (double-buffered)

        // tiny cross-warp sum (4 partials), redundant per-thread
        float4 acc = s_red[buf][0];
        #pragma unroll
        for (int w = 1; w < NW_; ++w) {
            const float4 v = s_red[buf][w];
            acc.x += v.x; acc.y += v.y; acc.z += v.z; acc.w += v.w;
        }
        a0 = acc.x; a1 = acc.y;

        if (tid == 0)
            *(float2*)(out_base + (size_t)t * O_) = make_float2(acc.z, acc.w);
    }
}

extern "C" void kernel_launch(void* const* d_in, const int* in_sizes, int n_in,
                              void* d_out, int out_size) {
    const float* input = (const float*)d_in[0];
    const float* noise = (const float*)d_in[1];
    const float* wi    = (const float*)d_in[2];
    const float* si    = (const float*)d_in[3];
    const float* m     = (const float*)d_in[4];
    const float* n     = (const float*)d_in[5];
    const float* wo    = (const float*)d_in[6];
    const float* so    = (const float*)d_in[7];
    const float* h0    = (const float*)d_in[8];

    float* out  = (float*)d_out;                         // (B,T,O) first
    float* traj = (float*)d_out + (size_t)B_ * T_ * O_;  // then (B,T,H)

    lowrank_rnn_kernel<<<B_, NT_>>>(input, noise, wi, si, m, n, wo, so, h0,
                                    out, traj);
}

// round 4
// speedup vs baseline: 2.0499x; 1.3836x over previous
#include <cuda_runtime.h>
#include <cuda_bf16.h>

#define B_ 64
#define T_ 1024
#define I_ 8
#define H_ 512
#define O_ 2
#define NOISE_STD_ 0.05f
#define ALPHA_ 0.2f

#define NT_  128            // threads per CTA
#define UPT_ 4              // hidden units per thread (NT_*UPT_ == H_)
#define NW_  (NT_ / 32)     // 4 warps

#define SA_   131072.0f     // 2^17 fixed-point scale for recurrence dots
#define SO_   2097152.0f    // 2^21 fixed-point scale for output dots

// Single-MUFU tanh (sm_75+). ~6e-4 rel err; downstream effect ~1e-4 on outputs.
__device__ __forceinline__ float tanh_mufu(float x) {
    float r;
    asm("tanh.approx.f32 %0, %1;" : "=f"(r) : "f"(x));
    return r;
}

// Warp-wide integer add-reduction, single instruction, result in all lanes.
__device__ __forceinline__ int redux_add_s32(int v) {
    int r;
    asm("redux.sync.add.s32 %0, %1, 0xffffffff;" : "=r"(r) : "r"(v));
    return r;
}

__global__ __launch_bounds__(NT_, 1)
void lowrank_rnn_kernel(const float* __restrict__ input,   // (B,T,I)
                        const float* __restrict__ noise,   // (B,T,H)
                        const float* __restrict__ wi,      // (I,H)
                        const float* __restrict__ si,      // (I,)
                        const float* __restrict__ m,       // (H,R)
                        const float* __restrict__ n,       // (H,R)
                        const float* __restrict__ wo,      // (H,O)
                        const float* __restrict__ so,      // (O,)
                        const float* __restrict__ h0,      // (H,)
                        float* __restrict__ out,           // (B,T,O)
                        float* __restrict__ traj)          // (B,T,H)
{
    __shared__ float s_in[T_ * I_];          // 32 KB: full input row for this batch
    __shared__ int4  s_red[2][NW_];          // per-warp int partials (a0,a1,o0,o1)

    const int b    = blockIdx.x;
    const int tid  = threadIdx.x;
    const int warp = tid >> 5;
    const int lane = tid & 31;
    const int k0   = tid * UPT_;             // first hidden unit of this thread

    // ---- stage input into smem, coalesced float4 ----
    {
        const float4* gin  = (const float4*)(input + (size_t)b * T_ * I_);
        float4*       sin4 = (float4*)s_in;
        #pragma unroll
        for (int i = 0; i < (T_ * I_ / 4) / NT_; ++i)     // 16 iters
            sin4[tid + i * NT_] = gin[tid + i * NT_];
    }

    // ---- per-thread weights (folded constants incl. fixed-point scales) ----
    float wif[I_][UPT_];
    #pragma unroll
    for (int i = 0; i < I_; ++i) {
        const float4 w = *(const float4*)(wi + i * H_ + k0);
        const float  s = si[i];
        wif[i][0] = w.x * s; wif[i][1] = w.y * s;
        wif[i][2] = w.z * s; wif[i][3] = w.w * s;
    }
    const float cm  = (ALPHA_ / (float)H_) / SA_;  // alpha/H and 1/Sa folded into m
    const float so0 = (so[0] / (float)H_) * SO_;   // 1/H and So folded into wo
    const float so1 = (so[1] / (float)H_) * SO_;
    float m0f[UPT_], m1f[UPT_], n0f[UPT_], n1f[UPT_], wo0f[UPT_], wo1f[UPT_];
    #pragma unroll
    for (int j = 0; j < UPT_; ++j) {
        const int k = k0 + j;
        m0f[j]  = m[k * 2 + 0] * cm;        m1f[j]  = m[k * 2 + 1] * cm;
        n0f[j]  = n[k * 2 + 0] * SA_;       n1f[j]  = n[k * 2 + 1] * SA_;
        wo0f[j] = wo[k * 2 + 0] * so0;      wo1f[j] = wo[k * 2 + 1] * so1;
    }

    float h[UPT_];
    {
        const float4 hh = *(const float4*)(h0 + k0);
        h[0] = hh.x; h[1] = hh.y; h[2] = hh.z; h[3] = hh.w;
    }

    const float* nz_base   = noise + (size_t)b * T_ * H_ + k0;
    float*       traj_base = traj  + (size_t)b * T_ * H_ + k0;
    float*       out_base  = out   + (size_t)b * T_ * O_;

    // ---- noise prefetch ring, depth 4 ----
    float4 ring[4];
    #pragma unroll
    for (int j = 0; j < 4; ++j)
        ring[j] = *(const float4*)(nz_base + (size_t)j * H_);

    // ---- pre-loop: a = n^T r_0 (into buffer 1; loop iter 0 reads buffer 0) ----
    float a0, a1;
    {
        float pa0 = 0.0f, pa1 = 0.0f;
        #pragma unroll
        for (int u = 0; u < UPT_; ++u) {
            const float r = tanh_mufu(h[u]);
            pa0 = fmaf(r, n0f[u], pa0);
            pa1 = fmaf(r, n1f[u], pa1);
        }
        int ia0 = redux_add_s32(__float2int_rn(pa0));
        int ia1 = redux_add_s32(__float2int_rn(pa1));
        if (lane == 0) s_red[1][warp] = make_int4(ia0, ia1, 0, 0);
        __syncthreads();                 // also covers s_in staging
        int sx = 0, sy = 0;
        #pragma unroll
        for (int w = 0; w < NW_; ++w) {
            const int4 v = s_red[1][w];
            sx += v.x; sy += v.y;
        }
        a0 = (float)sx; a1 = (float)sy;  // 1/Sa folded into m0f/m1f
    }

    // ---- main scan ----
    #pragma unroll 4
    for (int t = 0; t < T_; ++t) {
        const int j = t & 3;
        const float4 nz = ring[j];
        int tp = t + 4; if (tp > T_ - 1) tp = T_ - 1;            // clamp tail
        ring[j] = *(const float4*)(nz_base + (size_t)tp * H_);   // prefetch t+4

        // input projection p_t for 4 units (smem broadcast reads, off crit path)
        const float4 i0 = *(const float4*)(s_in + t * I_);
        const float4 i1 = *(const float4*)(s_in + t * I_ + 4);
        float p[UPT_];
        #pragma unroll
        for (int u = 0; u < UPT_; ++u) {
            float pp = i0.x * wif[0][u];
            pp = fmaf(i0.y, wif[1][u], pp);
            pp = fmaf(i0.z, wif[2][u], pp);
            pp = fmaf(i0.w, wif[3][u], pp);
            pp = fmaf(i1.x, wif[4][u], pp);
            pp = fmaf(i1.y, wif[5][u], pp);
            pp = fmaf(i1.z, wif[6][u], pp);
            pp = fmaf(i1.w, wif[7][u], pp);
            p[u] = pp;
        }
        const float nza[UPT_] = {nz.x, nz.y, nz.z, nz.w};

        // h' = 0.8h + 0.05nz + 0.2p + a0*m0f + a1*m1f ; r' = tanh(h')
        float pa0 = 0.0f, pa1 = 0.0f, po0 = 0.0f, po1 = 0.0f;
        #pragma unroll
        for (int u = 0; u < UPT_; ++u) {
            const float base = fmaf(NOISE_STD_, nza[u], ALPHA_ * p[u]);  // off path
            const float hb   = fmaf(1.0f - ALPHA_, h[u], base);          // off path
            float hx = fmaf(a0, m0f[u], hb);                             // path: 2 FMA
            hx       = fmaf(a1, m1f[u], hx);
            h[u] = hx;
            const float r = tanh_mufu(hx);                               // 1 MUFU
            pa0 = fmaf(r, n0f[u], pa0);     // scaled by Sa
            pa1 = fmaf(r, n1f[u], pa1);
            po0 = fmaf(r, wo0f[u], po0);    // scaled by So
            po1 = fmaf(r, wo1f[u], po1);
        }

        // traj[t] = h_{t+1}, coalesced STG.128
        *(float4*)(traj_base + (size_t)t * H_) = make_float4(h[0], h[1], h[2], h[3]);

        // fixed-point warp reduction: one REDUX per value (a-pair on crit path)
        const int ia0 = redux_add_s32(__float2int_rn(pa0));
        const int ia1 = redux_add_s32(__float2int_rn(pa1));
        const int io0 = redux_add_s32(__float2int_rn(po0));
        const int io1 = redux_add_s32(__float2int_rn(po1));

        const int buf = t & 1;
        if (lane == 0) s_red[buf][warp] = make_int4(ia0, ia1, io0, io1);
        __syncthreads();                  // one bar per step (double-buffered)

        // tiny cross-warp integer sum (4 partials), redundant per-thread
        const int4 v0 = s_red[buf][0];
        const int4 v1 = s_red[buf][1];
        const int4 v2 = s_red[buf][2];
        const int4 v3 = s_red[buf][3];
        a0 = (float)((v0.x + v1.x) + (v2.x + v3.x));
        a1 = (float)((v0.y + v1.y) + (v2.y + v3.y));

        if (tid == 0) {
            const float o0 = (float)((v0.z + v1.z) + (v2.z + v3.z)) * (1.0f / SO_);
            const float o1 = (float)((v0.w + v1.w) + (v2.w + v3.w)) * (1.0f / SO_);
            *(float2*)(out_base + (size_t)t * O_) = make_float2(o0, o1);
        }
    }
}

extern "C" void kernel_launch(void* const* d_in, const int* in_sizes, int n_in,
                              void* d_out, int out_size) {
    const float* input = (const float*)d_in[0];
    const float* noise = (const float*)d_in[1];
    const float* wi    = (const float*)d_in[2];
    const float* si    = (const float*)d_in[3];
    const float* m     = (const float*)d_in[4];
    const float* n     = (const float*)d_in[5];
    const float* wo    = (const float*)d_in[6];
    const float* so    = (const float*)d_in[7];
    const float* h0    = (const float*)d_in[8];

    float* out  = (float*)d_out;                         // (B,T,O) first
    float* traj = (float*)d_out + (size_t)B_ * T_ * O_;  // then (B,T,H)

    lowrank_rnn_kernel<<<B_, NT_>>>(input, noise, wi, si, m, n, wo, so, h0,
                                    out, traj);
}